// round 7
// baseline (speedup 1.0000x reference)
#include <cuda_runtime.h>

constexpr int Wd = 1024, Hd = 1024;
constexpr long HW = (long)Wd * Hd;
constexpr int CIN = 18;
constexpr float L2E = 1.4426950408889634f;

// Tile: 8 ch x 12 rows x 136 cols, TWO copies (normal + shifted-by-1-float).
constexpr int TP   = 136;
constexpr int TROW = 12;                  // 6 output rows + 6 halo
constexpr int TCH  = TROW * TP;           // 1632 floats per channel
constexpr int TILE_FLOATS = 8 * TCH;      // one copy
constexpr int SMEM_BYTES  = 2 * TILE_FLOATS * 4;   // 104,448 B

using u64 = unsigned long long;

__device__ __forceinline__ u64 pack2(float lo, float hi) {
    u64 r; asm("mov.b64 %0,{%1,%2};" : "=l"(r) : "f"(lo), "f"(hi)); return r;
}
__device__ __forceinline__ void unpack2(u64 v, float& lo, float& hi) {
    asm("mov.b64 {%0,%1},%2;" : "=f"(lo), "=f"(hi) : "l"(v));
}
__device__ __forceinline__ u64 fma2(u64 a, u64 b, u64 c) {
    u64 d; asm("fma.rn.f32x2 %0,%1,%2,%3;" : "=l"(d) : "l"(a), "l"(b), "l"(c)); return d;
}
__device__ __forceinline__ u64 add2(u64 a, u64 b) {
    u64 d; asm("add.rn.f32x2 %0,%1,%2;" : "=l"(d) : "l"(a), "l"(b)); return d;
}
__device__ __forceinline__ float ex2(float x) {
    float r; asm("ex2.approx.f32 %0,%1;" : "=f"(r) : "f"(x)); return r;
}
__device__ __forceinline__ u64 bcast2(float x) {
    unsigned u = __float_as_uint(x); return ((u64)u << 32) | u;
}
__device__ __forceinline__ u64 ldp(const float* p) {   // aligned LDS.64 pair
    return *(const u64*)p;
}

// ---------------------------------------------------------------------------
// Interior: block = 32 x-groups (4 px) x 6 rows. Halo staged to smem in two
// copies so every sliding-window f32 pair is a direct aligned LDS.64 u64 —
// zero pack MOVs in the main loop.
// ---------------------------------------------------------------------------
__device__ __forceinline__ void interior_path(const float* __restrict__ in,
                                              float* __restrict__ out,
                                              float* __restrict__ tn,   // normal
                                              float* __restrict__ ts,   // shifted
                                              int bx, int byi, int bz)
{
    const int g   = threadIdx.x;                 // 0..31
    const int ty  = threadIdx.y;                 // 0..5
    const int tid = ty * 32 + g;
    const int gxg = bx * 32 + g;
    const int x0  = 4 + gxg * 4;
    const int y   = 3 + byi * 6 + ty;

    const float* base = in + (long)bz * CIN * HW;

    // ---- Stage both tile copies (all 192 threads) ----
    {
        const int tx0 = bx * 128;
        const int gy0 = byi * 6;
        // 8ch * 12 rows * 34 float4 = 3264 slots
        for (int idx = tid; idx < 3264; idx += 192) {
            const int row = idx / 34;            // 0..95
            const int k   = idx - row * 34;      // 0..33
            const int c   = row / TROW;
            const int r   = row - c * TROW;
            int gx = tx0 + k * 4; if (gx > 1020) gx = 1020;   // clamped region unused
            int gy = gy0 + r;     if (gy > 1023) gy = 1023;   // clamped region unused
            int gxn = gx + 4;     if (gxn > 1020) gxn = 1020;
            const float* rp = base + c * HW + (long)gy * Wd;
            float4 v = *(const float4*)(rp + gx);
            float  nx = rp[gxn];                 // first elem of next group
            *(float4*)(tn + c * TCH + r * TP + k * 4) = v;
            float4 s; s.x = v.y; s.y = v.z; s.z = v.w; s.w = nx;
            *(float4*)(ts + c * TCH + r * TP + k * 4) = s;    // ts[m] == tn[m+1]
        }
    }
    __syncthreads();
    if (gxg > 253 || y > 1020) return;

    const long ctr = (long)y * Wd + x0;

    u64 rp2[8][2], mf2[8][2], K2[2], sxl2[2], syl2[2];
    {
        float Ks[4] = {0.f, 0.f, 0.f, 0.f};
        #pragma unroll
        for (int c = 0; c < 8; ++c) {
            float4 fv = *(const float4*)(tn + c * TCH + (ty + 3) * TP + g * 4 + 4);
            float4 pv = *(const float4*)(base + (8 + c) * HW + ctr);
            const float f4[4] = {fv.x, fv.y, fv.z, fv.w};
            const float p4[4] = {pv.x, pv.y, pv.z, pv.w};
            float rs[4], ms[4];
            #pragma unroll
            for (int p = 0; p < 4; ++p) {
                float r = -(p4[p] * p4[p]) * L2E;       // log2(e) folded in
                rs[p] = r;
                ms[p] = -2.f * r * f4[p];
                Ks[p] = fmaf(r * f4[p], f4[p], Ks[p]);
            }
            rp2[c][0] = pack2(rs[0], rs[1]); rp2[c][1] = pack2(rs[2], rs[3]);
            mf2[c][0] = pack2(ms[0], ms[1]); mf2[c][1] = pack2(ms[2], ms[3]);
        }
        K2[0] = pack2(Ks[0], Ks[1]); K2[1] = pack2(Ks[2], Ks[3]);
        float4 sv = *(const float4*)(base + 16 * HW + ctr);
        float4 tv = *(const float4*)(base + 17 * HW + ctr);
        sxl2[0] = pack2(-(sv.x*sv.x)*L2E, -(sv.y*sv.y)*L2E);
        sxl2[1] = pack2(-(sv.z*sv.z)*L2E, -(sv.w*sv.w)*L2E);
        syl2[0] = pack2(-(tv.x*tv.x)*L2E, -(tv.y*tv.y)*L2E);
        syl2[1] = pack2(-(tv.z*tv.z)*L2E, -(tv.w*tv.w)*L2E);
    }

    u64 acc2[3][2] = {}, ws2[2] = {};
    const int rowoff0 = ty * TP + g * 4;     // tile offset of this thread, row 0

    #pragma unroll 1        // body ~7KB/iter: stays inside I$
    for (int i = 0; i < 7; ++i) {
        const int ro = rowoff0 + i * TP;
        const u64 dyb = bcast2((float)((i - 3) * (i - 3)));

        u64 s2[7][2];
        {
            const u64 kd0 = fma2(syl2[0], dyb, K2[0]);
            const u64 kd1 = fma2(syl2[1], dyb, K2[1]);
            #pragma unroll
            for (int j = 0; j < 7; ++j) { s2[j][0] = kd0; s2[j][1] = kd1; }
        }

        #pragma unroll
        for (int c = 0; c < 8; ++c) {
            const float* rn = tn + c * TCH + ro;
            const float* rs = ts + c * TCH + ro;
            // pr[t-1] = (nv[t], nv[t+1]); odd t from shifted copy, even from normal
            u64 pr[9];
            pr[0] = ldp(rs + 0); pr[1] = ldp(rn + 2); pr[2] = ldp(rs + 2);
            pr[3] = ldp(rn + 4); pr[4] = ldp(rs + 4); pr[5] = ldp(rn + 6);
            pr[6] = ldp(rs + 6); pr[7] = ldp(rn + 8); pr[8] = ldp(rs + 8);
            #pragma unroll
            for (int j = 0; j < 7; ++j) {
                // s += fn * (rp*fn + mf)
                s2[j][0] = fma2(pr[j],     fma2(rp2[c][0], pr[j],     mf2[c][0]), s2[j][0]);
                s2[j][1] = fma2(pr[j + 2], fma2(rp2[c][1], pr[j + 2], mf2[c][1]), s2[j][1]);
            }
        }

        // Weights
        u64 w2a[7][2];
        #pragma unroll
        for (int j = 0; j < 7; ++j) {
            const u64 dxb = bcast2((float)((j - 3) * (j - 3)));
            #pragma unroll
            for (int pp = 0; pp < 2; ++pp) {
                u64 lw2 = fma2(sxl2[pp], dxb, s2[j][pp]);
                float a, b; unpack2(lw2, a, b);
                u64 w2 = pack2(ex2(a), ex2(b));
                w2a[j][pp] = w2;
                ws2[pp] = add2(ws2[pp], w2);
            }
        }

        // Accumulate output channels (same u64 pair loads, channels 0..2)
        #pragma unroll
        for (int c = 0; c < 3; ++c) {
            const float* rn = tn + c * TCH + ro;
            const float* rs = ts + c * TCH + ro;
            u64 pr[9];
            pr[0] = ldp(rs + 0); pr[1] = ldp(rn + 2); pr[2] = ldp(rs + 2);
            pr[3] = ldp(rn + 4); pr[4] = ldp(rs + 4); pr[5] = ldp(rn + 6);
            pr[6] = ldp(rs + 6); pr[7] = ldp(rn + 8); pr[8] = ldp(rs + 8);
            #pragma unroll
            for (int j = 0; j < 7; ++j) {
                acc2[c][0] = fma2(w2a[j][0], pr[j],     acc2[c][0]);
                acc2[c][1] = fma2(w2a[j][1], pr[j + 2], acc2[c][1]);
            }
        }
    }

    float ws[4];
    unpack2(ws2[0], ws[0], ws[1]); unpack2(ws2[1], ws[2], ws[3]);
    float inv[4];
    #pragma unroll
    for (int p = 0; p < 4; ++p) inv[p] = 1.f / ws[p];

    float* ob = out + (long)bz * 3 * HW + ctr;
    #pragma unroll
    for (int c = 0; c < 3; ++c) {
        float a0, a1, a2, a3;
        unpack2(acc2[c][0], a0, a1); unpack2(acc2[c][1], a2, a3);
        float4 o; o.x = a0 * inv[0]; o.y = a1 * inv[1]; o.z = a2 * inv[2]; o.w = a3 * inv[3];
        *(float4*)(ob + c * HW) = o;
    }
}

// ---------------------------------------------------------------------------
// Border ring: 14288 px/batch, bounds-checked; blocks scheduled first.
// ---------------------------------------------------------------------------
__device__ __forceinline__ void border_path(const float* __restrict__ in,
                                            float* __restrict__ out,
                                            int bid, int bz)
{
    const int tid = threadIdx.y * 32 + threadIdx.x;
    int r = bid * 192 + tid;
    if (r >= 14288) return;
    int x, y;
    if (r < 3072)        { y = r >> 10;                x = r & 1023; }
    else if (r < 6144)   { r -= 3072;  y = 1021 + (r >> 10); x = r & 1023; }
    else if (r < 10216)  { r -= 6144;  y = 3 + (r >> 2);     x = r & 3; }
    else                 { r -= 10216; y = 3 + (r >> 2);     x = 1020 + (r & 3); }

    const float* base = in + (long)bz * CIN * HW;
    const long ctr = (long)y * Wd + x;

    float f[8], rp[8];
    #pragma unroll
    for (int c = 0; c < 8; ++c) {
        f[c] = base[c * HW + ctr];
        float pv = base[(8 + c) * HW + ctr];
        rp[c] = -(pv * pv);
    }
    float sv = base[16 * HW + ctr];
    float tv = base[17 * HW + ctr];
    const float sxl = -(sv * sv), syl = -(tv * tv);

    float a0 = 0.f, a1 = 0.f, a2 = 0.f, ws = 0.f;
    for (int i = 0; i < 7; ++i) {
        const int gy = y + i - 3;
        if (gy < 0 || gy >= Hd) continue;
        const float dy2 = (float)((i - 3) * (i - 3));
        for (int j = 0; j < 7; ++j) {
            const int gx = x + j - 3;
            if (gx < 0 || gx >= Wd) continue;
            const float dx2 = (float)((j - 3) * (j - 3));
            const float* q = base + (long)gy * Wd + gx;
            float fn[8];
            float lw = fmaf(sxl, dx2, syl * dy2);
            #pragma unroll
            for (int c = 0; c < 8; ++c) {
                fn[c] = q[c * HW];
                float d = fn[c] - f[c];
                lw = fmaf(rp[c], d * d, lw);
            }
            float w = __expf(lw);
            ws += w;
            a0 = fmaf(w, fn[0], a0);
            a1 = fmaf(w, fn[1], a1);
            a2 = fmaf(w, fn[2], a2);
        }
    }
    float* ob = out + (long)bz * 3 * HW + ctr;
    const float inv = 1.f / ws;
    ob[0]      = a0 * inv;
    ob[HW]     = a1 * inv;
    ob[2 * HW] = a2 * inv;
}

__global__ __launch_bounds__(192, 2)
void bilat_fused(const float* __restrict__ in, float* __restrict__ out)
{
    extern __shared__ __align__(16) float smem[];

    if (blockIdx.y < 10) {
        border_path(in, out, blockIdx.y * 8 + blockIdx.x, blockIdx.z);
    } else {
        interior_path(in, out, smem, smem + TILE_FLOATS,
                      blockIdx.x, blockIdx.y - 10, blockIdx.z);
    }
}

extern "C" void kernel_launch(void* const* d_in, const int* in_sizes, int n_in,
                              void* d_out, int out_size)
{
    const float* in = (const float*)d_in[0];
    float* out = (float*)d_out;

    cudaFuncSetAttribute(bilat_fused,
                         cudaFuncAttributeMaxDynamicSharedMemorySize, SMEM_BYTES);

    dim3 blk(32, 6, 1);
    // y: 10 border rows (80 blocks, 75 used) + 170 interior rows (6 out-rows each)
    dim3 grd(8, 10 + 170, 2);
    bilat_fused<<<grd, blk, SMEM_BYTES>>>(in, out);
}